// round 3
// baseline (speedup 1.0000x reference)
#include <cuda_runtime.h>
#include <cuda_bf16.h>
#include <cstdint>

// ---------------------------------------------------------------------------
// AliasFreeConv: modulated 3x3 conv (demod) + up2x (12-tap sep) + lrelu +
// down2x (12-tap sep).
// Shapes: x[8,512,64,64], conv VALID -> [8,512,62,62], up -> [.,.,128,128],
// down -> [8,512,64,64] (margin crop is 0).
// ---------------------------------------------------------------------------

#define Bn    8
#define CIN   512
#define COUT  512
#define Hs    64
#define Ws    64
#define OH    62
#define OW    62
#define TAPS  12

__device__ float g_s[Bn * CIN];          // modulation s[b,ci]
__device__ float g_alpha[Bn * COUT];     // wscale*demod/(1+eps)
__device__ float g_wsum[COUT * CIN];     // sum_k conv_w^2
__device__ float g_conv[(size_t)Bn * COUT * OH * OW];        // 63 MB
__device__ float g_uph [(size_t)Bn * COUT * OH * 128];       // 130 MB
__device__ float g_upv [(size_t)Bn * COUT * 128 * 128];      // 268 MB
__device__ float g_dnh [(size_t)Bn * COUT * 128 * 64];       // 134 MB

#define LIN_SCALE 0.04419417382415922f   /* 1/sqrt(512) */
#define WSCALE    0.014731391274719738f  /* 1/sqrt(512*9) */
#define SQRT2     1.4142135623730951f
#define NEG_SLOPE 0.2f
#define EPSV      1e-8f

// ---------------------------------------------------------------------------
// s[b,ci] = (style[b] . mod_w[ci]) * lin_scale + mod_b[ci]   (warp per output)
// ---------------------------------------------------------------------------
__global__ void style_kernel(const float* __restrict__ style,
                             const float* __restrict__ mod_w,
                             const float* __restrict__ mod_b) {
    int w = (blockIdx.x * blockDim.x + threadIdx.x) >> 5;
    int lane = threadIdx.x & 31;
    if (w >= Bn * CIN) return;
    int b = w >> 9, ci = w & 511;
    const float* st = style + b * 512;
    const float* mw = mod_w + ci * 512;
    float acc = 0.f;
    #pragma unroll 4
    for (int j = lane; j < 512; j += 32) acc += st[j] * mw[j];
    #pragma unroll
    for (int o = 16; o; o >>= 1) acc += __shfl_xor_sync(0xffffffffu, acc, o);
    if (lane == 0) g_s[w] = acc * LIN_SCALE + mod_b[ci];
}

// wsum[co,ci] = sum over 3x3 of conv_w^2
__global__ void wsum_kernel(const float* __restrict__ cw) {
    int idx = blockIdx.x * blockDim.x + threadIdx.x;
    if (idx >= COUT * CIN) return;
    const float* p = cw + (size_t)idx * 9;
    float s = 0.f;
    #pragma unroll
    for (int k = 0; k < 9; k++) s += p[k] * p[k];
    g_wsum[idx] = s;
}

// alpha[b,co] = wscale * rsqrt(wscale^2 * S + eps) / (1+eps),
//   S = sum_ci wsum[co,ci] * s[b,ci]^2
__global__ void alpha_kernel() {
    int w = (blockIdx.x * blockDim.x + threadIdx.x) >> 5;
    int lane = threadIdx.x & 31;
    if (w >= Bn * COUT) return;
    int b = w >> 9, co = w & 511;
    const float* ws = g_wsum + co * 512;
    const float* sp = g_s + b * 512;
    float acc = 0.f;
    #pragma unroll 4
    for (int j = lane; j < 512; j += 32) { float sv = sp[j]; acc += ws[j] * sv * sv; }
    #pragma unroll
    for (int o = 16; o; o >>= 1) acc += __shfl_xor_sync(0xffffffffu, acc, o);
    if (lane == 0) {
        float demod = rsqrtf(WSCALE * WSCALE * acc + EPSV);
        g_alpha[w] = WSCALE * demod / (1.f + EPSV);
    }
}

// ---------------------------------------------------------------------------
// 3x3 conv, VALID: g_conv[b,co,y,x] = alpha[b,co] *
//     sum_{ci,kh,kw} conv_w[co,ci,kh,kw] * s[b,ci] * x[b,ci,y+kh,x+kw] + act_b
// Block: 64 co x (4 rows x 32 cols) outputs; thread: 4 co x 8 px.
// ci processed in chunks of 8 through shared memory.
// ---------------------------------------------------------------------------
#define CK 8
__global__ __launch_bounds__(256, 2)
void conv_kernel(const float* __restrict__ x, const float* __restrict__ cw,
                 const float* __restrict__ act_b) {
    __shared__ __align__(16) float sx[CK * 6 * 36];   // 8 ci x 6 rows x 34(+2) cols
    __shared__ __align__(16) float sw[CK * 9 * 68];   // 8 ci x 9 taps x 64(+4) co

    const int x0  = blockIdx.x * 32;
    const int y0  = blockIdx.y * 4;
    const int b   = blockIdx.z >> 3;
    const int co0 = (blockIdx.z & 7) * 64;
    const int tid = threadIdx.x;
    const int cog = tid >> 4;       // 0..15 -> 4 co each
    const int pg  = tid & 15;
    const int row = pg >> 2;        // 0..3
    const int cg  = pg & 3;         // 0..3 -> 8 cols each

    float acc[4][8];
    #pragma unroll
    for (int i = 0; i < 4; i++)
        #pragma unroll
        for (int j = 0; j < 8; j++) acc[i][j] = 0.f;

    const float* xb = x + (size_t)b * CIN * Hs * Ws;
    const float* sb = g_s + b * CIN;

    for (int ci0 = 0; ci0 < CIN; ci0 += CK) {
        // load modulated input patch: sx[c][r][col] = s[b,ci]*x[...]
        for (int e = tid; e < CK * 6 * 34; e += 256) {
            int c = e / 204; int rem = e - c * 204;
            int r = rem / 34; int col = rem - r * 34;
            int gy = y0 + r, gx = x0 + col;
            float v = 0.f;
            if (gy < Hs && gx < Ws)
                v = xb[((size_t)(ci0 + c) * Hs + gy) * Ws + gx] * sb[ci0 + c];
            sx[(c * 6 + r) * 36 + col] = v;
        }
        // load weight chunk, coalesced over (ci,k); padded stride 68 vs bank conflicts
        for (int e = tid; e < CK * 9 * 64; e += 256) {
            int co = e / 72; int f = e - co * 72;
            int ci = f / 9;  int kk = f - ci * 9;
            sw[(ci * 9 + kk) * 68 + co] =
                cw[((size_t)(co0 + co) * CIN + ci0 + ci) * 9 + kk];
        }
        __syncthreads();

        #pragma unroll 2
        for (int c = 0; c < CK; c++) {
            #pragma unroll
            for (int kh = 0; kh < 3; kh++) {
                float xr[10];
                const float* sxp = &sx[(c * 6 + row + kh) * 36 + cg * 8];
                #pragma unroll
                for (int j = 0; j < 10; j++) xr[j] = sxp[j];
                #pragma unroll
                for (int kw = 0; kw < 3; kw++) {
                    const float4 w4 =
                        *(const float4*)&sw[(c * 9 + kh * 3 + kw) * 68 + cog * 4];
                    #pragma unroll
                    for (int j = 0; j < 8; j++) {
                        float xv = xr[kw + j];
                        acc[0][j] += w4.x * xv;
                        acc[1][j] += w4.y * xv;
                        acc[2][j] += w4.z * xv;
                        acc[3][j] += w4.w * xv;
                    }
                }
            }
        }
        __syncthreads();
    }

    const int gy = y0 + row;
    if (gy < OH) {
        #pragma unroll
        for (int i = 0; i < 4; i++) {
            int co = co0 + cog * 4 + i;
            float a  = g_alpha[b * COUT + co];
            float bb = act_b[co];
            float* dst = g_conv + (((size_t)b * COUT + co) * OH + gy) * OW;
            #pragma unroll
            for (int j = 0; j < 8; j++) {
                int gx = x0 + cg * 8 + j;
                if (gx < OW) dst[gx] = acc[i][j] * a + bb;
            }
        }
    }
}

// ---------------------------------------------------------------------------
// Separable upfirdn stages (index math derived from conv_general_dilated):
//  up  (u=2, p=(8,7)):  out[o] = 2 * sum_t f[t]*in[(o+3-t)/2]  ((o+3-t) even)
//  down(d=2, p=(5,5)):  out[o] =     sum_t f[t]*in[2o+6-t]
// ---------------------------------------------------------------------------
__global__ void uph_kernel(const float* __restrict__ uf) {
    int idx = blockIdx.x * 256 + threadIdx.x;             // [bc][62][128]
    if (idx >= Bn * COUT * OH * 128) return;
    int o  = idx & 127;
    int y  = (idx >> 7) % OH;
    int bc = idx / (OH * 128);
    const float* row = g_conv + ((size_t)bc * OH + y) * OW;
    float v = 0.f;
    #pragma unroll
    for (int t = 0; t < TAPS; t++) {
        int n = o + 3 - t;
        if (!(n & 1)) {
            int j = n >> 1;
            if (j >= 0 && j < OW) v += uf[t] * row[j];
        }
    }
    g_uph[idx] = 2.0f * v;
}

__global__ void upv_kernel(const float* __restrict__ uf) {
    int idx = blockIdx.x * 256 + threadIdx.x;             // [bc][128][128]
    if (idx >= Bn * COUT * 128 * 128) return;
    int xx = idx & 127;
    int oy = (idx >> 7) & 127;
    int bc = idx >> 14;
    const float* base = g_uph + (size_t)bc * OH * 128 + xx;
    float v = 0.f;
    #pragma unroll
    for (int t = 0; t < TAPS; t++) {
        int n = oy + 3 - t;
        if (!(n & 1)) {
            int j = n >> 1;
            if (j >= 0 && j < OH) v += uf[t] * base[j * 128];
        }
    }
    v *= 2.0f;
    v = (v >= 0.f ? v : NEG_SLOPE * v) * SQRT2;           // leaky relu * sqrt(2)
    g_upv[idx] = v;
}

__global__ void dnh_kernel(const float* __restrict__ df) {
    int idx = blockIdx.x * 256 + threadIdx.x;             // [bc][128][64]
    if (idx >= Bn * COUT * 128 * 64) return;
    int o  = idx & 63;
    int y  = (idx >> 6) & 127;
    int bc = idx >> 13;
    const float* row = g_upv + ((size_t)bc * 128 + y) * 128;
    float v = 0.f;
    #pragma unroll
    for (int t = 0; t < TAPS; t++) {
        int p = 2 * o + 6 - t;
        if (p >= 0 && p < 128) v += df[t] * row[p];
    }
    g_dnh[idx] = v;
}

__global__ void dnv_kernel(const float* __restrict__ df, float* __restrict__ out) {
    int idx = blockIdx.x * 256 + threadIdx.x;             // [bc][64][64]
    if (idx >= Bn * COUT * 64 * 64) return;
    int xx = idx & 63;
    int oy = (idx >> 6) & 63;
    int bc = idx >> 12;
    const float* base = g_dnh + (size_t)bc * 128 * 64 + xx;
    float v = 0.f;
    #pragma unroll
    for (int t = 0; t < TAPS; t++) {
        int p = 2 * oy + 6 - t;
        if (p >= 0 && p < 128) v += df[t] * base[p * 64];
    }
    out[idx] = v;
}

// ---------------------------------------------------------------------------
extern "C" void kernel_launch(void* const* d_in, const int* in_sizes, int n_in,
                              void* d_out, int out_size) {
    const float* x      = (const float*)d_in[0];
    const float* style  = (const float*)d_in[1];
    const float* mod_w  = (const float*)d_in[2];
    const float* mod_b  = (const float*)d_in[3];
    const float* conv_w = (const float*)d_in[4];
    const float* act_b  = (const float*)d_in[5];
    const float* up_f   = (const float*)d_in[6];
    const float* dn_f   = (const float*)d_in[7];
    float* out = (float*)d_out;

    // modulation scalars
    style_kernel<<<(Bn * CIN * 32 + 255) / 256, 256>>>(style, mod_w, mod_b);
    wsum_kernel<<<(COUT * CIN + 255) / 256, 256>>>(conv_w);
    alpha_kernel<<<(Bn * COUT * 32 + 255) / 256, 256>>>();

    // modulated conv
    dim3 cgrid(2, 16, Bn * 8);
    conv_kernel<<<cgrid, 256>>>(x, conv_w, act_b);

    // up 2x (h then v + lrelu), down 2x (h then v)
    {
        int n = Bn * COUT * OH * 128;
        uph_kernel<<<(n + 255) / 256, 256>>>(up_f);
    }
    {
        int n = Bn * COUT * 128 * 128;
        upv_kernel<<<(n + 255) / 256, 256>>>(up_f);
    }
    {
        int n = Bn * COUT * 128 * 64;
        dnh_kernel<<<(n + 255) / 256, 256>>>(dn_f);
    }
    {
        int n = Bn * COUT * 64 * 64;
        dnv_kernel<<<(n + 255) / 256, 256>>>(dn_f, out);
    }
    (void)in_sizes; (void)n_in; (void)out_size;
}